// round 11
// baseline (speedup 1.0000x reference)
#include <cuda_runtime.h>

#define HID 64
#define GATES 192
#define BATCH 4096
#define TSTEPS 512
#define TILE_B 32
#define NCTA 128
#define NTHREADS 512

typedef unsigned long long ull;

// smem layout (float offsets)
#define OFF_W0   0        // Whh0 packed [k2][pair][blk][gi][kl] (12288)
#define OFF_WA   12288    // Wih1 packed
#define OFF_WB   24576    // Whh1 packed
#define OFF_H0   36864    // h0: 3 buffers x [32][64] swizzled (6144)
#define OFF_H1   43008    // h1: 2 buffers (4096)
#define OFF_PX   47104    // PX pre-acts (Wih1-r x h0): 2 buffers x [32][64] (4096)
#define OFF_WIH0 51200    // Wih0 col-major [2][192], r/z scaled 0.5
#define OFF_MB0  51584
#define OFF_B0NX 51712
#define OFF_B0NH 51776
#define OFF_MB1  51840
#define OFF_B1NA 51968
#define OFF_B1NB 52032
#define OFF_WP   52096
#define OFF_XS   52224    // x staging float2[2][32]
#define SMEM_FLOATS 52352
#define SMEM_BYTES (SMEM_FLOATS * 4)   // 209408 B

__device__ __forceinline__ ull ffma2(ull a, ull b, ull c) {
    ull d; asm("fma.rn.f32x2 %0, %1, %2, %3;" : "=l"(d) : "l"(a), "l"(b), "l"(c)); return d;
}
__device__ __forceinline__ void unpk(ull v, float& lo, float& hi) {
    asm("mov.b64 {%0, %1}, %2;" : "=f"(lo), "=f"(hi) : "l"(v));
}
__device__ __forceinline__ float tanhx(float v) {
    float y; asm("tanh.approx.f32 %0, %1;" : "=f"(y) : "f"(v)); return y;
}
// swizzle: chunk index XORed with b>>2 (distinct across 8 lane-groups)
__device__ __forceinline__ int haddr(int b, int j) {
    return b * 64 + ((((j >> 2) ^ (b >> 2)) << 2) | (j & 3));
}
__device__ __forceinline__ int hchunk(int b, int c) {
    return b * 64 + (((c ^ (b >> 2)) & 15) << 2);
}

extern __shared__ float smem[];

__global__ void __launch_bounds__(NTHREADS, 1)
gru2_r11_kernel(const float* __restrict__ x,
                const float* __restrict__ Wih0, const float* __restrict__ Whh0,
                const float* __restrict__ bih0, const float* __restrict__ bhh0,
                const float* __restrict__ Wih1, const float* __restrict__ Whh1,
                const float* __restrict__ bih1, const float* __restrict__ bhh1,
                const float* __restrict__ Wp,   const float* __restrict__ bp,
                float* __restrict__ out)
{
    const int tid = threadIdx.x;
    const int b0  = blockIdx.x * TILE_B;

    float* w0s  = smem + OFF_W0;
    float* was  = smem + OFF_WA;
    float* wbs  = smem + OFF_WB;
    float* h0bs = smem + OFF_H0;
    float* h1bs = smem + OFF_H1;
    float* pxs  = smem + OFF_PX;
    float* wih0s = smem + OFF_WIH0;
    float2* xsf = (float2*)(smem + OFF_XS);

    // ---- prologue: pack weights as {w_k, w_k+1} per gate, [k2][pair][blk] ----
    for (int d = tid; d < HID * GATES; d += NTHREADS) {
        int g = d >> 6, k = d & 63;        // source [192][64] row-major
        float s = (g < 128) ? 0.5f : 1.0f;
        int blk = g >> 6, j = g & 63;
        int fpos = (k >> 1) * 384 + (j >> 1) * 12 + blk * 4 + (j & 1) * 2 + (k & 1);
        w0s[fpos] = Whh0[d] * s;
        was[fpos] = Wih1[d] * s;
        wbs[fpos] = Whh1[d] * s;
    }
    for (int g = tid; g < GATES; g += NTHREADS) {
        float s = (g < 128) ? 0.5f : 1.0f;
        wih0s[g]         = Wih0[2 * g]     * s;
        wih0s[GATES + g] = Wih0[2 * g + 1] * s;
    }
    if (tid < 128) {
        smem[OFF_MB0 + tid] = 0.5f * (bih0[tid] + bhh0[tid]);
        smem[OFF_MB1 + tid] = 0.5f * (bih1[tid] + bhh1[tid]);
        smem[OFF_WP + tid]  = Wp[tid];
    }
    if (tid < 64) {
        smem[OFF_B0NX + tid] = bih0[128 + tid];
        smem[OFF_B0NH + tid] = bhh0[128 + tid];
        smem[OFF_B1NA + tid] = bih1[128 + tid];
        smem[OFF_B1NB + tid] = bhh1[128 + tid];
    }
    // zero h0(3) + h1(2) + PX(2) = 14336 floats contiguous
    for (int d = tid; d < 14336; d += NTHREADS) h0bs[d] = 0.0f;
    if (tid < TILE_B)
        xsf[tid] = *(const float2*)(x + (size_t)(b0 + tid) * 2);   // x(0) -> slot 0
    __syncthreads();

    // tiling within each 256-thread group: pair = gate-pair, bg = batch group of 4
    const int gtid = tid & 255;
    const int pair = gtid >> 3;         // 0..31
    const int bg   = gtid & 7;          // 0..7
    const int j0   = pair * 2;
    const int bb   = bg * 4;
    const int ppos = pair ^ (bg & 3);   // PX bank-swizzled pair slot

    int rowb[4];
    #pragma unroll
    for (int i = 0; i < 4; ++i) rowb[i] = (bb + i) * 64;

    const float* wbase0 = w0s + pair * 12;
    const float* wbaseA = was + pair * 12;
    const float* wbaseB = wbs + pair * 12;

    // pipeline: iter j -> A: GEMM1+gates L0 (t=j) AND PX=Wih1_r x h0(j-1);
    //                    B: L1 step t=j-2 (Wih1-z/n x h0(j-2) + Whh1 x h1(j-3) + PX)
    for (int it = 0; it <= TSTEPS + 1; ++it) {
        if (tid < 256) {
            if (it <= TSTEPS) {
                const int m0 = it % 3;             // write buf: h0(it)
                const int m1 = (it + 2) % 3;       // read buf:  h0(it-1)
                const float* h0r = h0bs + m1 * 2048;
                float* h0w       = h0bs + m0 * 2048;
                float* pxw       = pxs + (((it + 1) & 1) << 11);   // PX(it-1)

                float2 xnext = make_float2(0.0f, 0.0f);
                if (gtid < TILE_B && it + 1 < TSTEPS)
                    xnext = *(const float2*)(x + ((size_t)(it + 1) * BATCH + b0 + gtid) * 2);

                ull ar[2][4], az[2][4], an[2][4], pr[2][4];
                #pragma unroll
                for (int i = 0; i < 4; ++i) {
                    ar[0][i] = 0; ar[1][i] = 0; az[0][i] = 0; az[1][i] = 0;
                    an[0][i] = 0; an[1][i] = 0; pr[0][i] = 0; pr[1][i] = 0;
                }

                #pragma unroll 4
                for (int k4 = 0; k4 < 16; ++k4) {
                    const int coff = ((k4 ^ bg) << 2);
                    ulonglong2 h[4];
                    #pragma unroll
                    for (int i = 0; i < 4; ++i)
                        h[i] = *(const ulonglong2*)(h0r + rowb[i] + coff);
                    #pragma unroll
                    for (int kp = 0; kp < 2; ++kp) {
                        int woff = (k4 * 2 + kp) * 384;
                        const float* w = wbase0 + woff;
                        ulonglong2 wr = *(const ulonglong2*)(w);
                        ulonglong2 wz = *(const ulonglong2*)(w + 4);
                        ulonglong2 wn = *(const ulonglong2*)(w + 8);
                        ulonglong2 wp = *(const ulonglong2*)(wbaseA + woff);   // Wih1 r-block
                        #pragma unroll
                        for (int i = 0; i < 4; ++i) {
                            ull hv = kp ? h[i].y : h[i].x;
                            ar[0][i] = ffma2(wr.x, hv, ar[0][i]);
                            ar[1][i] = ffma2(wr.y, hv, ar[1][i]);
                            az[0][i] = ffma2(wz.x, hv, az[0][i]);
                            az[1][i] = ffma2(wz.y, hv, az[1][i]);
                            an[0][i] = ffma2(wn.x, hv, an[0][i]);
                            an[1][i] = ffma2(wn.y, hv, an[1][i]);
                            pr[0][i] = ffma2(wp.x, hv, pr[0][i]);
                            pr[1][i] = ffma2(wp.y, hv, pr[1][i]);
                        }
                    }
                }

                // constants reloaded per step
                float2 mb0r2 = *(const float2*)(smem + OFF_MB0 + j0);
                float2 mb0z2 = *(const float2*)(smem + OFF_MB0 + 64 + j0);
                float2 b0nx2 = *(const float2*)(smem + OFF_B0NX + j0);
                float2 b0nh2 = *(const float2*)(smem + OFF_B0NH + j0);
                float2 xwr0 = *(const float2*)(wih0s + j0);
                float2 xwz0 = *(const float2*)(wih0s + 64 + j0);
                float2 xwn0 = *(const float2*)(wih0s + 128 + j0);
                float2 xwr1 = *(const float2*)(wih0s + GATES + j0);
                float2 xwz1 = *(const float2*)(wih0s + GATES + 64 + j0);
                float2 xwn1 = *(const float2*)(wih0s + GATES + 128 + j0);

                #pragma unroll
                for (int i = 0; i < 4; ++i) {
                    int b = bb + i;
                    float2 xv = xsf[(it & 1) * TILE_B + b];
                    float2 hp = *(const float2*)(h0r + haddr(b, j0));
                    float o[2];
                    #pragma unroll
                    for (int g = 0; g < 2; ++g) {
                        float rl, rh, zl, zh, nl, nh;
                        unpk(ar[g][i], rl, rh);
                        unpk(az[g][i], zl, zh);
                        unpk(an[g][i], nl, nh);
                        float mbr = g ? mb0r2.y : mb0r2.x;
                        float mbz = g ? mb0z2.y : mb0z2.x;
                        float bnx = g ? b0nx2.y : b0nx2.x;
                        float bnh = g ? b0nh2.y : b0nh2.x;
                        float wr0 = g ? xwr0.y : xwr0.x, wr1 = g ? xwr1.y : xwr1.x;
                        float wz0 = g ? xwz0.y : xwz0.x, wz1 = g ? xwz1.y : xwz1.x;
                        float wn0 = g ? xwn0.y : xwn0.x, wn1 = g ? xwn1.y : xwn1.x;
                        float rsum = fmaf(xv.y, wr1, fmaf(xv.x, wr0, (rl + rh) + mbr));
                        float zsum = fmaf(xv.y, wz1, fmaf(xv.x, wz0, (zl + zh) + mbz));
                        float sr = fmaf(tanhx(rsum), 0.5f, 0.5f);
                        float sz = fmaf(tanhx(zsum), 0.5f, 0.5f);
                        float hn = (nl + nh) + bnh;
                        float xn = fmaf(xv.y, wn1, fmaf(xv.x, wn0, bnx));
                        float n = tanhx(fmaf(sr, hn, xn));
                        float hprev = g ? hp.y : hp.x;
                        o[g] = fmaf(sz, hprev - n, n);
                    }
                    *(float2*)(h0w + haddr(b, j0)) = make_float2(o[0], o[1]);
                    // PX write: Wih1-r pre-acts for L1 step (it-1)
                    float p0l, p0h, p1l, p1h;
                    unpk(pr[0][i], p0l, p0h);
                    unpk(pr[1][i], p1l, p1h);
                    *(float2*)(pxw + b * 64 + ppos * 2) = make_float2(p0l + p0h, p1l + p1h);
                }

                if (gtid < TILE_B)
                    xsf[((it + 1) & 1) * TILE_B + gtid] = xnext;
            }
        } else {
            if (it >= 2) {
                // ======== group B: L1 step t=it-2 ========
                const float* hAr = h0bs + ((it + 1) % 3) * 2048;   // h0(it-2)
                const float* h1r = h1bs + (((it + 1) & 1) << 11);  // h1(it-3)
                float* h1w       = h1bs + ((it & 1) << 11);        // h1(it-2)
                const float* pxr = pxs + ((it & 1) << 11);         // PX(it-2)

                ull cr[2][4], cz[2][4], cA[2][4], cB[2][4];
                #pragma unroll
                for (int i = 0; i < 4; ++i) {
                    cr[0][i] = 0; cr[1][i] = 0; cz[0][i] = 0; cz[1][i] = 0;
                    cA[0][i] = 0; cA[1][i] = 0; cB[0][i] = 0; cB[1][i] = 0;
                }

                #pragma unroll 2
                for (int k4 = 0; k4 < 16; ++k4) {
                    const int coff = ((k4 ^ bg) << 2);
                    ulonglong2 hA[4], hB[4];
                    #pragma unroll
                    for (int i = 0; i < 4; ++i) {
                        int off = rowb[i] + coff;
                        hA[i] = *(const ulonglong2*)(hAr + off);
                        hB[i] = *(const ulonglong2*)(h1r + off);
                    }
                    #pragma unroll
                    for (int kp = 0; kp < 2; ++kp) {
                        int woff = (k4 * 2 + kp) * 384;
                        const float* wa = wbaseA + woff;
                        const float* wb = wbaseB + woff;
                        ulonglong2 waz = *(const ulonglong2*)(wa + 4);
                        ulonglong2 wan = *(const ulonglong2*)(wa + 8);
                        ulonglong2 wbr = *(const ulonglong2*)(wb);
                        ulonglong2 wbz = *(const ulonglong2*)(wb + 4);
                        ulonglong2 wbn = *(const ulonglong2*)(wb + 8);
                        #pragma unroll
                        for (int i = 0; i < 4; ++i) {
                            ull av = kp ? hA[i].y : hA[i].x;
                            ull bv = kp ? hB[i].y : hB[i].x;
                            cr[0][i] = ffma2(wbr.x, bv, cr[0][i]);
                            cr[1][i] = ffma2(wbr.y, bv, cr[1][i]);
                            cz[0][i] = ffma2(waz.x, av, cz[0][i]);
                            cz[0][i] = ffma2(wbz.x, bv, cz[0][i]);
                            cz[1][i] = ffma2(waz.y, av, cz[1][i]);
                            cz[1][i] = ffma2(wbz.y, bv, cz[1][i]);
                            cA[0][i] = ffma2(wan.x, av, cA[0][i]);
                            cA[1][i] = ffma2(wan.y, av, cA[1][i]);
                            cB[0][i] = ffma2(wbn.x, bv, cB[0][i]);
                            cB[1][i] = ffma2(wbn.y, bv, cB[1][i]);
                        }
                    }
                }

                float2 mb1r2 = *(const float2*)(smem + OFF_MB1 + j0);
                float2 mb1z2 = *(const float2*)(smem + OFF_MB1 + 64 + j0);
                float2 b1nA2 = *(const float2*)(smem + OFF_B1NA + j0);
                float2 b1nB2 = *(const float2*)(smem + OFF_B1NB + j0);

                #pragma unroll
                for (int i = 0; i < 4; ++i) {
                    int b = bb + i;
                    float2 hp = *(const float2*)(h1r + haddr(b, j0));
                    float2 pxv = *(const float2*)(pxr + b * 64 + ppos * 2);
                    float o[2];
                    #pragma unroll
                    for (int g = 0; g < 2; ++g) {
                        float rl, rh, zl, zh, al, ah, bl, bh;
                        unpk(cr[g][i], rl, rh);
                        unpk(cz[g][i], zl, zh);
                        unpk(cA[g][i], al, ah);
                        unpk(cB[g][i], bl, bh);
                        float mbr = g ? mb1r2.y : mb1r2.x;
                        float mbz = g ? mb1z2.y : mb1z2.x;
                        float bnA = g ? b1nA2.y : b1nA2.x;
                        float bnB = g ? b1nB2.y : b1nB2.x;
                        float pxg = g ? pxv.y : pxv.x;
                        float sr = fmaf(tanhx((rl + rh) + pxg + mbr), 0.5f, 0.5f);
                        float sz = fmaf(tanhx((zl + zh) + mbz), 0.5f, 0.5f);
                        float xn = (al + ah) + bnA;
                        float hn = (bl + bh) + bnB;
                        float n = tanhx(fmaf(sr, hn, xn));
                        float hprev = g ? hp.y : hp.x;
                        o[g] = fmaf(sz, hprev - n, n);
                    }
                    *(float2*)(h1w + haddr(b, j0)) = make_float2(o[0], o[1]);
                }
            }
        }
        __syncthreads();
    }

    // ---- final projection: h0(T-1) in buf (T-1)%3 = 1; h1(T-1) in buf (T-1)&1 = 1 ----
    if (tid < TILE_B) {
        int b = tid;
        const float* wps = smem + OFF_WP;
        const float* h0f = h0bs + ((TSTEPS - 1) % 3) * 2048;
        const float* h1f = h1bs + (((TSTEPS - 1) & 1) << 11);
        float s = bp[0];
        #pragma unroll
        for (int c = 0; c < 16; ++c) {
            float4 h4 = *(const float4*)(h0f + hchunk(b, c));
            int k = c * 4;
            s = fmaf(h4.x, wps[k], s);
            s = fmaf(h4.y, wps[k + 1], s);
            s = fmaf(h4.z, wps[k + 2], s);
            s = fmaf(h4.w, wps[k + 3], s);
        }
        #pragma unroll
        for (int c = 0; c < 16; ++c) {
            float4 h4 = *(const float4*)(h1f + hchunk(b, c));
            int k = 64 + c * 4;
            s = fmaf(h4.x, wps[k], s);
            s = fmaf(h4.y, wps[k + 1], s);
            s = fmaf(h4.z, wps[k + 2], s);
            s = fmaf(h4.w, wps[k + 3], s);
        }
        out[b0 + tid] = s;
    }
}

extern "C" void kernel_launch(void* const* d_in, const int* in_sizes, int n_in,
                              void* d_out, int out_size) {
    const float* x    = (const float*)d_in[0];
    const float* Wih0 = (const float*)d_in[1];
    const float* Whh0 = (const float*)d_in[2];
    const float* bih0 = (const float*)d_in[3];
    const float* bhh0 = (const float*)d_in[4];
    const float* Wih1 = (const float*)d_in[5];
    const float* Whh1 = (const float*)d_in[6];
    const float* bih1 = (const float*)d_in[7];
    const float* bhh1 = (const float*)d_in[8];
    const float* Wp   = (const float*)d_in[9];
    const float* bp   = (const float*)d_in[10];
    float* out = (float*)d_out;

    cudaFuncSetAttribute(gru2_r11_kernel,
                         cudaFuncAttributeMaxDynamicSharedMemorySize, SMEM_BYTES);
    gru2_r11_kernel<<<NCTA, NTHREADS, SMEM_BYTES>>>(
        x, Wih0, Whh0, bih0, bhh0, Wih1, Whh1, bih1, bhh1, Wp, bp, out);
}

// round 14
// speedup vs baseline: 1.0011x; 1.0011x over previous
#include <cuda_runtime.h>

#define HID 64
#define GATES 192
#define BATCH 4096
#define TSTEPS 512
#define TILE_B 32
#define NCTA 128
#define NTHREADS 512

typedef unsigned long long ull;

// smem layout (float offsets)
#define OFF_W0   0        // Whh0 packed [k2][pair][blk][gi][kl] (12288)
#define OFF_WA   12288    // Wih1 packed
#define OFF_WB   24576    // Whh1 packed
#define OFF_H0   36864    // h0: 3 buffers x [32][64] swizzled (6144)
#define OFF_H1   43008    // h1: 2 buffers (4096)
#define OFF_PX   47104    // PX pre-acts (Wih1-r x h0): 2 buffers x [32][64] (4096)
#define OFF_WIH0 51200    // Wih0 col-major [2][192], r/z scaled 0.5
#define OFF_MB0  51584
#define OFF_B0NX 51712
#define OFF_B0NH 51776
#define OFF_MB1  51840
#define OFF_B1NA 51968
#define OFF_B1NB 52032
#define OFF_WP   52096
#define OFF_XS   52224    // x staging float2[2][32]
#define SMEM_FLOATS 52352
#define SMEM_BYTES (SMEM_FLOATS * 4)   // 209408 B

__device__ __forceinline__ ull ffma2(ull a, ull b, ull c) {
    ull d; asm("fma.rn.f32x2 %0, %1, %2, %3;" : "=l"(d) : "l"(a), "l"(b), "l"(c)); return d;
}
__device__ __forceinline__ void unpk(ull v, float& lo, float& hi) {
    asm("mov.b64 {%0, %1}, %2;" : "=f"(lo), "=f"(hi) : "l"(v));
}
__device__ __forceinline__ float tanhx(float v) {
    float y; asm("tanh.approx.f32 %0, %1;" : "=f"(y) : "f"(v)); return y;
}
// swizzle: chunk index XORed with b>>2 (distinct across 8 lane-groups)
__device__ __forceinline__ int haddr(int b, int j) {
    return b * 64 + ((((j >> 2) ^ (b >> 2)) << 2) | (j & 3));
}
__device__ __forceinline__ int hchunk(int b, int c) {
    return b * 64 + (((c ^ (b >> 2)) & 15) << 2);
}

extern __shared__ float smem[];

__global__ void __launch_bounds__(NTHREADS, 1)
gru2_r11_kernel(const float* __restrict__ x,
                const float* __restrict__ Wih0, const float* __restrict__ Whh0,
                const float* __restrict__ bih0, const float* __restrict__ bhh0,
                const float* __restrict__ Wih1, const float* __restrict__ Whh1,
                const float* __restrict__ bih1, const float* __restrict__ bhh1,
                const float* __restrict__ Wp,   const float* __restrict__ bp,
                float* __restrict__ out)
{
    const int tid = threadIdx.x;
    const int b0  = blockIdx.x * TILE_B;

    float* w0s  = smem + OFF_W0;
    float* was  = smem + OFF_WA;
    float* wbs  = smem + OFF_WB;
    float* h0bs = smem + OFF_H0;
    float* h1bs = smem + OFF_H1;
    float* pxs  = smem + OFF_PX;
    float* wih0s = smem + OFF_WIH0;
    float2* xsf = (float2*)(smem + OFF_XS);

    // ---- prologue: pack weights as {w_k, w_k+1} per gate, [k2][pair][blk] ----
    for (int d = tid; d < HID * GATES; d += NTHREADS) {
        int g = d >> 6, k = d & 63;        // source [192][64] row-major
        float s = (g < 128) ? 0.5f : 1.0f;
        int blk = g >> 6, j = g & 63;
        int fpos = (k >> 1) * 384 + (j >> 1) * 12 + blk * 4 + (j & 1) * 2 + (k & 1);
        w0s[fpos] = Whh0[d] * s;
        was[fpos] = Wih1[d] * s;
        wbs[fpos] = Whh1[d] * s;
    }
    for (int g = tid; g < GATES; g += NTHREADS) {
        float s = (g < 128) ? 0.5f : 1.0f;
        wih0s[g]         = Wih0[2 * g]     * s;
        wih0s[GATES + g] = Wih0[2 * g + 1] * s;
    }
    if (tid < 128) {
        smem[OFF_MB0 + tid] = 0.5f * (bih0[tid] + bhh0[tid]);
        smem[OFF_MB1 + tid] = 0.5f * (bih1[tid] + bhh1[tid]);
        smem[OFF_WP + tid]  = Wp[tid];
    }
    if (tid < 64) {
        smem[OFF_B0NX + tid] = bih0[128 + tid];
        smem[OFF_B0NH + tid] = bhh0[128 + tid];
        smem[OFF_B1NA + tid] = bih1[128 + tid];
        smem[OFF_B1NB + tid] = bhh1[128 + tid];
    }
    // zero h0(3) + h1(2) + PX(2) = 14336 floats contiguous
    for (int d = tid; d < 14336; d += NTHREADS) h0bs[d] = 0.0f;
    if (tid < TILE_B)
        xsf[tid] = *(const float2*)(x + (size_t)(b0 + tid) * 2);   // x(0) -> slot 0
    __syncthreads();

    // tiling within each 256-thread group: pair = gate-pair, bg = batch group of 4
    const int gtid = tid & 255;
    const int pair = gtid >> 3;         // 0..31
    const int bg   = gtid & 7;          // 0..7
    const int j0   = pair * 2;
    const int bb   = bg * 4;
    const int ppos = pair ^ (bg & 3);   // PX bank-swizzled pair slot

    int rowb[4];
    #pragma unroll
    for (int i = 0; i < 4; ++i) rowb[i] = (bb + i) * 64;

    const float* wbase0 = w0s + pair * 12;
    const float* wbaseA = was + pair * 12;
    const float* wbaseB = wbs + pair * 12;

    // pipeline: iter j -> A: GEMM1+gates L0 (t=j) AND PX=Wih1_r x h0(j-1);
    //                    B: L1 step t=j-2 (Wih1-z/n x h0(j-2) + Whh1 x h1(j-3) + PX)
    for (int it = 0; it <= TSTEPS + 1; ++it) {
        if (tid < 256) {
            if (it <= TSTEPS) {
                const int m0 = it % 3;             // write buf: h0(it)
                const int m1 = (it + 2) % 3;       // read buf:  h0(it-1)
                const float* h0r = h0bs + m1 * 2048;
                float* h0w       = h0bs + m0 * 2048;
                float* pxw       = pxs + (((it + 1) & 1) << 11);   // PX(it-1)

                float2 xnext = make_float2(0.0f, 0.0f);
                if (gtid < TILE_B && it + 1 < TSTEPS)
                    xnext = *(const float2*)(x + ((size_t)(it + 1) * BATCH + b0 + gtid) * 2);

                ull ar[2][4], az[2][4], an[2][4], pr[2][4];
                #pragma unroll
                for (int i = 0; i < 4; ++i) {
                    ar[0][i] = 0; ar[1][i] = 0; az[0][i] = 0; az[1][i] = 0;
                    an[0][i] = 0; an[1][i] = 0; pr[0][i] = 0; pr[1][i] = 0;
                }

                #pragma unroll 4
                for (int k4 = 0; k4 < 16; ++k4) {
                    const int coff = ((k4 ^ bg) << 2);
                    ulonglong2 h[4];
                    #pragma unroll
                    for (int i = 0; i < 4; ++i)
                        h[i] = *(const ulonglong2*)(h0r + rowb[i] + coff);
                    #pragma unroll
                    for (int kp = 0; kp < 2; ++kp) {
                        int woff = (k4 * 2 + kp) * 384;
                        const float* w = wbase0 + woff;
                        ulonglong2 wr = *(const ulonglong2*)(w);
                        ulonglong2 wz = *(const ulonglong2*)(w + 4);
                        ulonglong2 wn = *(const ulonglong2*)(w + 8);
                        ulonglong2 wp = *(const ulonglong2*)(wbaseA + woff);   // Wih1 r-block
                        #pragma unroll
                        for (int i = 0; i < 4; ++i) {
                            ull hv = kp ? h[i].y : h[i].x;
                            ar[0][i] = ffma2(wr.x, hv, ar[0][i]);
                            ar[1][i] = ffma2(wr.y, hv, ar[1][i]);
                            az[0][i] = ffma2(wz.x, hv, az[0][i]);
                            az[1][i] = ffma2(wz.y, hv, az[1][i]);
                            an[0][i] = ffma2(wn.x, hv, an[0][i]);
                            an[1][i] = ffma2(wn.y, hv, an[1][i]);
                            pr[0][i] = ffma2(wp.x, hv, pr[0][i]);
                            pr[1][i] = ffma2(wp.y, hv, pr[1][i]);
                        }
                    }
                }

                // constants reloaded per step
                float2 mb0r2 = *(const float2*)(smem + OFF_MB0 + j0);
                float2 mb0z2 = *(const float2*)(smem + OFF_MB0 + 64 + j0);
                float2 b0nx2 = *(const float2*)(smem + OFF_B0NX + j0);
                float2 b0nh2 = *(const float2*)(smem + OFF_B0NH + j0);
                float2 xwr0 = *(const float2*)(wih0s + j0);
                float2 xwz0 = *(const float2*)(wih0s + 64 + j0);
                float2 xwn0 = *(const float2*)(wih0s + 128 + j0);
                float2 xwr1 = *(const float2*)(wih0s + GATES + j0);
                float2 xwz1 = *(const float2*)(wih0s + GATES + 64 + j0);
                float2 xwn1 = *(const float2*)(wih0s + GATES + 128 + j0);

                #pragma unroll
                for (int i = 0; i < 4; ++i) {
                    int b = bb + i;
                    float2 xv = xsf[(it & 1) * TILE_B + b];
                    float2 hp = *(const float2*)(h0r + haddr(b, j0));
                    float o[2];
                    #pragma unroll
                    for (int g = 0; g < 2; ++g) {
                        float rl, rh, zl, zh, nl, nh;
                        unpk(ar[g][i], rl, rh);
                        unpk(az[g][i], zl, zh);
                        unpk(an[g][i], nl, nh);
                        float mbr = g ? mb0r2.y : mb0r2.x;
                        float mbz = g ? mb0z2.y : mb0z2.x;
                        float bnx = g ? b0nx2.y : b0nx2.x;
                        float bnh = g ? b0nh2.y : b0nh2.x;
                        float wr0 = g ? xwr0.y : xwr0.x, wr1 = g ? xwr1.y : xwr1.x;
                        float wz0 = g ? xwz0.y : xwz0.x, wz1 = g ? xwz1.y : xwz1.x;
                        float wn0 = g ? xwn0.y : xwn0.x, wn1 = g ? xwn1.y : xwn1.x;
                        float rsum = fmaf(xv.y, wr1, fmaf(xv.x, wr0, (rl + rh) + mbr));
                        float zsum = fmaf(xv.y, wz1, fmaf(xv.x, wz0, (zl + zh) + mbz));
                        float sr = fmaf(tanhx(rsum), 0.5f, 0.5f);
                        float sz = fmaf(tanhx(zsum), 0.5f, 0.5f);
                        float hn = (nl + nh) + bnh;
                        float xn = fmaf(xv.y, wn1, fmaf(xv.x, wn0, bnx));
                        float n = tanhx(fmaf(sr, hn, xn));
                        float hprev = g ? hp.y : hp.x;
                        o[g] = fmaf(sz, hprev - n, n);
                    }
                    *(float2*)(h0w + haddr(b, j0)) = make_float2(o[0], o[1]);
                    // PX write: Wih1-r pre-acts for L1 step (it-1)
                    float p0l, p0h, p1l, p1h;
                    unpk(pr[0][i], p0l, p0h);
                    unpk(pr[1][i], p1l, p1h);
                    *(float2*)(pxw + b * 64 + ppos * 2) = make_float2(p0l + p0h, p1l + p1h);
                }

                if (gtid < TILE_B)
                    xsf[((it + 1) & 1) * TILE_B + gtid] = xnext;
            }
        } else {
            if (it >= 2) {
                // ======== group B: L1 step t=it-2 ========
                const float* hAr = h0bs + ((it + 1) % 3) * 2048;   // h0(it-2)
                const float* h1r = h1bs + (((it + 1) & 1) << 11);  // h1(it-3)
                float* h1w       = h1bs + ((it & 1) << 11);        // h1(it-2)
                const float* pxr = pxs + ((it & 1) << 11);         // PX(it-2)

                ull cr[2][4], cz[2][4], cA[2][4], cB[2][4];
                #pragma unroll
                for (int i = 0; i < 4; ++i) {
                    cr[0][i] = 0; cr[1][i] = 0; cz[0][i] = 0; cz[1][i] = 0;
                    cA[0][i] = 0; cA[1][i] = 0; cB[0][i] = 0; cB[1][i] = 0;
                }

                #pragma unroll 2
                for (int k4 = 0; k4 < 16; ++k4) {
                    const int coff = ((k4 ^ bg) << 2);
                    ulonglong2 hA[4], hB[4];
                    #pragma unroll
                    for (int i = 0; i < 4; ++i) {
                        int off = rowb[i] + coff;
                        hA[i] = *(const ulonglong2*)(hAr + off);
                        hB[i] = *(const ulonglong2*)(h1r + off);
                    }
                    #pragma unroll
                    for (int kp = 0; kp < 2; ++kp) {
                        int woff = (k4 * 2 + kp) * 384;
                        const float* wa = wbaseA + woff;
                        const float* wb = wbaseB + woff;
                        ulonglong2 waz = *(const ulonglong2*)(wa + 4);
                        ulonglong2 wan = *(const ulonglong2*)(wa + 8);
                        ulonglong2 wbr = *(const ulonglong2*)(wb);
                        ulonglong2 wbz = *(const ulonglong2*)(wb + 4);
                        ulonglong2 wbn = *(const ulonglong2*)(wb + 8);
                        #pragma unroll
                        for (int i = 0; i < 4; ++i) {
                            ull av = kp ? hA[i].y : hA[i].x;
                            ull bv = kp ? hB[i].y : hB[i].x;
                            cr[0][i] = ffma2(wbr.x, bv, cr[0][i]);
                            cr[1][i] = ffma2(wbr.y, bv, cr[1][i]);
                            cz[0][i] = ffma2(waz.x, av, cz[0][i]);
                            cz[0][i] = ffma2(wbz.x, bv, cz[0][i]);
                            cz[1][i] = ffma2(waz.y, av, cz[1][i]);
                            cz[1][i] = ffma2(wbz.y, bv, cz[1][i]);
                            cA[0][i] = ffma2(wan.x, av, cA[0][i]);
                            cA[1][i] = ffma2(wan.y, av, cA[1][i]);
                            cB[0][i] = ffma2(wbn.x, bv, cB[0][i]);
                            cB[1][i] = ffma2(wbn.y, bv, cB[1][i]);
                        }
                    }
                }

                float2 mb1r2 = *(const float2*)(smem + OFF_MB1 + j0);
                float2 mb1z2 = *(const float2*)(smem + OFF_MB1 + 64 + j0);
                float2 b1nA2 = *(const float2*)(smem + OFF_B1NA + j0);
                float2 b1nB2 = *(const float2*)(smem + OFF_B1NB + j0);

                #pragma unroll
                for (int i = 0; i < 4; ++i) {
                    int b = bb + i;
                    float2 hp = *(const float2*)(h1r + haddr(b, j0));
                    float2 pxv = *(const float2*)(pxr + b * 64 + ppos * 2);
                    float o[2];
                    #pragma unroll
                    for (int g = 0; g < 2; ++g) {
                        float rl, rh, zl, zh, al, ah, bl, bh;
                        unpk(cr[g][i], rl, rh);
                        unpk(cz[g][i], zl, zh);
                        unpk(cA[g][i], al, ah);
                        unpk(cB[g][i], bl, bh);
                        float mbr = g ? mb1r2.y : mb1r2.x;
                        float mbz = g ? mb1z2.y : mb1z2.x;
                        float bnA = g ? b1nA2.y : b1nA2.x;
                        float bnB = g ? b1nB2.y : b1nB2.x;
                        float pxg = g ? pxv.y : pxv.x;
                        float sr = fmaf(tanhx((rl + rh) + pxg + mbr), 0.5f, 0.5f);
                        float sz = fmaf(tanhx((zl + zh) + mbz), 0.5f, 0.5f);
                        float xn = (al + ah) + bnA;
                        float hn = (bl + bh) + bnB;
                        float n = tanhx(fmaf(sr, hn, xn));
                        float hprev = g ? hp.y : hp.x;
                        o[g] = fmaf(sz, hprev - n, n);
                    }
                    *(float2*)(h1w + haddr(b, j0)) = make_float2(o[0], o[1]);
                }
            }
        }
        __syncthreads();
    }

    // ---- final projection: h0(T-1) in buf (T-1)%3 = 1; h1(T-1) in buf (T-1)&1 = 1 ----
    if (tid < TILE_B) {
        int b = tid;
        const float* wps = smem + OFF_WP;
        const float* h0f = h0bs + ((TSTEPS - 1) % 3) * 2048;
        const float* h1f = h1bs + (((TSTEPS - 1) & 1) << 11);
        float s = bp[0];
        #pragma unroll
        for (int c = 0; c < 16; ++c) {
            float4 h4 = *(const float4*)(h0f + hchunk(b, c));
            int k = c * 4;
            s = fmaf(h4.x, wps[k], s);
            s = fmaf(h4.y, wps[k + 1], s);
            s = fmaf(h4.z, wps[k + 2], s);
            s = fmaf(h4.w, wps[k + 3], s);
        }
        #pragma unroll
        for (int c = 0; c < 16; ++c) {
            float4 h4 = *(const float4*)(h1f + hchunk(b, c));
            int k = 64 + c * 4;
            s = fmaf(h4.x, wps[k], s);
            s = fmaf(h4.y, wps[k + 1], s);
            s = fmaf(h4.z, wps[k + 2], s);
            s = fmaf(h4.w, wps[k + 3], s);
        }
        out[b0 + tid] = s;
    }
}

extern "C" void kernel_launch(void* const* d_in, const int* in_sizes, int n_in,
                              void* d_out, int out_size) {
    const float* x    = (const float*)d_in[0];
    const float* Wih0 = (const float*)d_in[1];
    const float* Whh0 = (const float*)d_in[2];
    const float* bih0 = (const float*)d_in[3];
    const float* bhh0 = (const float*)d_in[4];
    const float* Wih1 = (const float*)d_in[5];
    const float* Whh1 = (const float*)d_in[6];
    const float* bih1 = (const float*)d_in[7];
    const float* bhh1 = (const float*)d_in[8];
    const float* Wp   = (const float*)d_in[9];
    const float* bp   = (const float*)d_in[10];
    float* out = (float*)d_out;

    cudaFuncSetAttribute(gru2_r11_kernel,
                         cudaFuncAttributeMaxDynamicSharedMemorySize, SMEM_BYTES);
    gru2_r11_kernel<<<NCTA, NTHREADS, SMEM_BYTES>>>(
        x, Wih0, Whh0, bih0, bhh0, Wih1, Whh1, bih1, bhh1, Wp, bp, out);
}